// round 1
// baseline (speedup 1.0000x reference)
#include <cuda_runtime.h>

// Problem constants (fixed by the dataset)
constexpr int NN  = 50000;   // nodes
constexpr int EE  = 800000;  // edges
constexpr int PER = 200000;  // edges per emulsion order (EE/4)
constexpr int H   = 64;      // hidden dim

// ---------------- scratch (static device globals; no allocation) ----------
__device__ float g_x[NN * H];        // node features
__device__ float g_A[NN * H];        // dst-side pre-GEMM
__device__ float g_B[NN * H];        // src-side pre-GEMM
__device__ int   g_deg[5 * NN];      // degrees: 4 src-slices + 1 dst
__device__ int   g_off[5 * (NN + 1)];
__device__ int   g_cur[5 * (NN + 1)];
__device__ int   g_nbr[2 * EE];      // [0,EE): src-CSR stores dst; [EE,2EE): dst-CSR stores src
__device__ float g_cef[EE];          // edge feature, src-CSR order

// ---------------- CSR build ------------------------------------------------
__global__ void k_zero(int* p, int n) {
    int i = blockIdx.x * blockDim.x + threadIdx.x;
    if (i < n) p[i] = 0;
}

__global__ void k_hist(const int* __restrict__ ei) {
    int e = blockIdx.x * blockDim.x + threadIdx.x;
    if (e >= EE) return;
    int s = ei[e], d = ei[EE + e];
    int sl = e / PER;
    atomicAdd(&g_deg[sl * NN + s], 1);
    atomicAdd(&g_deg[4 * NN + d], 1);
}

// grid = 5 blocks (one per array), block = 1024
__global__ void k_scan() {
    int a = blockIdx.x;
    const int* deg = g_deg + a * NN;
    int* off = g_off + a * (NN + 1);
    int* cur = g_cur + a * (NN + 1);
    int t = threadIdx.x;
    const int CH = (NN + 1023) / 1024;  // 49
    int begin = t * CH;
    int end = begin + CH; if (end > NN) end = NN; if (begin > NN) begin = NN;
    int s = 0;
    for (int i = begin; i < end; i++) s += deg[i];
    __shared__ int sh[1024];
    sh[t] = s;
    __syncthreads();
    for (int d = 1; d < 1024; d <<= 1) {
        int v = 0;
        if (t >= d) v = sh[t - d];
        __syncthreads();
        if (t >= d) sh[t] += v;
        __syncthreads();
    }
    int pre = (t == 0) ? 0 : sh[t - 1];
    for (int i = begin; i < end; i++) {
        off[i] = pre; cur[i] = pre;
        pre += deg[i];
    }
    if (t == 1023) off[NN] = sh[1023];
}

__global__ void k_scatter(const int* __restrict__ ei, const float* __restrict__ ef) {
    int e = blockIdx.x * blockDim.x + threadIdx.x;
    if (e >= EE) return;
    int s = ei[e], d = ei[EE + e];
    int sl = e / PER;
    int p = atomicAdd(&g_cur[sl * (NN + 1) + s], 1);
    int idx = sl * PER + p;
    g_nbr[idx] = d;
    g_cef[idx] = ef[e];
    int q = atomicAdd(&g_cur[4 * (NN + 1) + d], 1);
    g_nbr[EE + q] = s;
}

// ---------------- single GEMM (+bias, +relu): out[N,64] = relu(x[N,K]@W[K,64]+b)
// block = 64 threads, one output column per thread, weights in registers.
template <int K, int RELU>
__global__ void k_gemm1(const float* __restrict__ xin, const float* __restrict__ W,
                        const float* __restrict__ bias, float* __restrict__ out,
                        int rowsPerBlock) {
    int t = threadIdx.x;  // 0..63 = column
    float w[K];
#pragma unroll
    for (int k = 0; k < K; k++) w[k] = W[k * H + t];
    float bv = bias[t];
    __shared__ float xs[4][K];
    int row0 = blockIdx.x * rowsPerBlock;
    int row1 = row0 + rowsPerBlock; if (row1 > NN) row1 = NN;
    for (int r = row0; r < row1; r += 4) {
        for (int i = t; i < 4 * K; i += 64) xs[i / K][i % K] = xin[r * K + i];
        __syncthreads();
        float a0 = bv, a1 = bv, a2 = bv, a3 = bv;
#pragma unroll
        for (int k = 0; k < K; k++) {
            float wv = w[k];
            a0 = fmaf(xs[0][k], wv, a0);
            a1 = fmaf(xs[1][k], wv, a1);
            a2 = fmaf(xs[2][k], wv, a2);
            a3 = fmaf(xs[3][k], wv, a3);
        }
        if (RELU) {
            a0 = fmaxf(a0, 0.f); a1 = fmaxf(a1, 0.f);
            a2 = fmaxf(a2, 0.f); a3 = fmaxf(a3, 0.f);
        }
        out[(r + 0) * H + t] = a0;
        out[(r + 1) * H + t] = a1;
        out[(r + 2) * H + t] = a2;
        out[(r + 3) * H + t] = a3;
        __syncthreads();
    }
}

// ---------------- fused dual GEMM: A = x@(W[0:64]-W[64:128]) (+bias?),
//                                   B = x@W[64:128]           (+bias?)
// block = 128 threads: t<64 -> A column t, t>=64 -> B column t-64.
template <int BIAS_A, int BIAS_B>
__global__ void k_gemm2(const float* __restrict__ xin, const float* __restrict__ W,
                        const float* __restrict__ bias, float* __restrict__ outA,
                        float* __restrict__ outB, int rowsPerBlock) {
    int t = threadIdx.x;
    int c = t & 63;
    bool isB = t >= 64;
    float w[H];
    if (!isB) {
#pragma unroll
        for (int k = 0; k < H; k++) w[k] = W[k * H + c] - W[(H + k) * H + c];
    } else {
#pragma unroll
        for (int k = 0; k < H; k++) w[k] = W[(H + k) * H + c];
    }
    float bv = (isB ? BIAS_B : BIAS_A) ? bias[c] : 0.f;
    __shared__ float4 xs[4][16];
    int row0 = blockIdx.x * rowsPerBlock;
    int row1 = row0 + rowsPerBlock; if (row1 > NN) row1 = NN;
    float* o = isB ? outB : outA;
    for (int r = row0; r < row1; r += 4) {
        const float4* src = (const float4*)(xin + r * H);
        for (int i = t; i < 64; i += 128) ((float4*)xs)[i] = src[i];
        __syncthreads();
        float a0 = bv, a1 = bv, a2 = bv, a3 = bv;
#pragma unroll
        for (int k = 0; k < 16; k++) {
            float4 v0 = xs[0][k], v1 = xs[1][k], v2 = xs[2][k], v3 = xs[3][k];
            a0 = fmaf(v0.x, w[4 * k + 0], a0); a0 = fmaf(v0.y, w[4 * k + 1], a0);
            a0 = fmaf(v0.z, w[4 * k + 2], a0); a0 = fmaf(v0.w, w[4 * k + 3], a0);
            a1 = fmaf(v1.x, w[4 * k + 0], a1); a1 = fmaf(v1.y, w[4 * k + 1], a1);
            a1 = fmaf(v1.z, w[4 * k + 2], a1); a1 = fmaf(v1.w, w[4 * k + 3], a1);
            a2 = fmaf(v2.x, w[4 * k + 0], a2); a2 = fmaf(v2.y, w[4 * k + 1], a2);
            a2 = fmaf(v2.z, w[4 * k + 2], a2); a2 = fmaf(v2.w, w[4 * k + 3], a2);
            a3 = fmaf(v3.x, w[4 * k + 0], a3); a3 = fmaf(v3.y, w[4 * k + 1], a3);
            a3 = fmaf(v3.z, w[4 * k + 2], a3); a3 = fmaf(v3.w, w[4 * k + 3], a3);
        }
        o[(r + 0) * H + c] = a0;
        o[(r + 1) * H + c] = a1;
        o[(r + 2) * H + c] = a2;
        o[(r + 3) * H + c] = a3;
        __syncthreads();
    }
}

// ---------------- EmulsionConv edge pass (one order slice) -----------------
// warp per node n (aggregating at src): x[n] = (x[n] + sum_e relu(A[dst_e]+B[n]+ef_e*w2)) / 2
__global__ void k_em_edge(const int* __restrict__ off, const int* __restrict__ nbr,
                          const float* __restrict__ cef, const float* __restrict__ w2) {
    int warp = (blockIdx.x * blockDim.x + threadIdx.x) >> 5;
    int lane = threadIdx.x & 31;
    if (warp >= NN) return;
    int n = warp;
    int e0 = off[n], e1 = off[n + 1];
    float yb0 = g_B[n * H + lane], yb1 = g_B[n * H + 32 + lane];
    float w20 = w2[lane], w21 = w2[32 + lane];
    float a0 = 0.f, a1 = 0.f;
    for (int e = e0; e < e1; e++) {
        int d = nbr[e];
        float f = cef[e];
        float m0 = g_A[d * H + lane] + fmaf(f, w20, yb0);
        float m1 = g_A[d * H + 32 + lane] + fmaf(f, w21, yb1);
        a0 += fmaxf(m0, 0.f);
        a1 += fmaxf(m1, 0.f);
    }
    g_x[n * H + lane]      = (g_x[n * H + lane] + a0) * 0.5f;
    g_x[n * H + 32 + lane] = (g_x[n * H + 32 + lane] + a1) * 0.5f;
}

// ---------------- EdgeConv edge pass ---------------------------------------
// warp per node n (aggregating at dst): x[n] = max(0, max_e (A[n]+B[src_e]))
__global__ void k_ec_edge(const int* __restrict__ off, const int* __restrict__ nbr) {
    int warp = (blockIdx.x * blockDim.x + threadIdx.x) >> 5;
    int lane = threadIdx.x & 31;
    if (warp >= NN) return;
    int n = warp;
    int e0 = off[n], e1 = off[n + 1];
    float za0 = g_A[n * H + lane], za1 = g_A[n * H + 32 + lane];
    float a0 = 0.f, a1 = 0.f;  // relu floor: max over messages of relu == max(0, max msg)
    for (int e = e0; e < e1; e++) {
        int s = nbr[e];
        a0 = fmaxf(a0, za0 + g_B[s * H + lane]);
        a1 = fmaxf(a1, za1 + g_B[s * H + 32 + lane]);
    }
    g_x[n * H + lane]      = a0;
    g_x[n * H + 32 + lane] = a1;
}

// ---------------- output head: out[N,10] = x@ow[64,10] + ob -----------------
__global__ void k_out(const float* __restrict__ ow, const float* __restrict__ ob,
                      float* __restrict__ out) {
    __shared__ float w[64 * 10];
    __shared__ float b[10];
    int t = threadIdx.x;
    for (int i = t; i < 640; i += blockDim.x) w[i] = ow[i];
    if (t < 10) b[t] = ob[t];
    __syncthreads();
    int idx = blockIdx.x * blockDim.x + t;
    if (idx >= NN * 10) return;
    int n = idx / 10, c = idx % 10;
    float acc = b[c];
#pragma unroll
    for (int k = 0; k < 64; k++) acc = fmaf(g_x[n * H + k], w[k * 10 + c], acc);
    out[idx] = acc;
}

// ---------------- orchestration --------------------------------------------
extern "C" void kernel_launch(void* const* d_in, const int* in_sizes, int n_in,
                              void* d_out, int out_size) {
    const float* x0  = (const float*)d_in[0];
    const int*   ei  = (const int*)d_in[1];
    const float* ef  = (const float*)d_in[2];
    const float* lw[3] = {(const float*)d_in[3], (const float*)d_in[5], (const float*)d_in[7]};
    const float* lb[3] = {(const float*)d_in[4], (const float*)d_in[6], (const float*)d_in[8]};
    const float* emw = (const float*)d_in[9];   // [3,129,64]
    const float* emb = (const float*)d_in[10];  // [3,64]
    const float* ecw = (const float*)d_in[11];  // [3,128,64]
    const float* ecb = (const float*)d_in[12];  // [3,64]
    const float* ow  = (const float*)d_in[13];
    const float* ob  = (const float*)d_in[14];

    float *gx, *gA, *gB, *gcef;
    int *gdeg, *goff, *gnbr;
    cudaGetSymbolAddress((void**)&gx,   g_x);
    cudaGetSymbolAddress((void**)&gA,   g_A);
    cudaGetSymbolAddress((void**)&gB,   g_B);
    cudaGetSymbolAddress((void**)&gcef, g_cef);
    cudaGetSymbolAddress((void**)&gdeg, g_deg);
    cudaGetSymbolAddress((void**)&goff, g_off);
    cudaGetSymbolAddress((void**)&gnbr, g_nbr);

    // CSR build (per launch, deterministic workload)
    k_zero<<<(5 * NN + 255) / 256, 256>>>(gdeg, 5 * NN);
    k_hist<<<(EE + 255) / 256, 256>>>(ei);
    k_scan<<<5, 1024>>>();
    k_scatter<<<(EE + 255) / 256, 256>>>(ei, ef);

    const int RPB1 = 52;
    const int G1 = (NN + RPB1 - 1) / RPB1;
    const int RPB2 = 88;
    const int G2 = (NN + RPB2 - 1) / RPB2;
    const int GE = (NN * 32 + 255) / 256;  // warp per node

    // lin0 (K=10) + 3x (lin, EmulsionConv x4 orders)
    k_gemm1<10, 1><<<G1, 64>>>(x0, lw[0], lb[0], gx, RPB1);
    for (int L = 0; L < 3; L++) {
        if (L > 0) k_gemm1<64, 1><<<G1, 64>>>(gx, lw[L], lb[L], gx, RPB1);
        const float* W = emw + L * 129 * H;
        const float* b = emb + L * H;
        for (int o = 0; o < 4; o++) {
            k_gemm2<0, 1><<<G2, 128>>>(gx, W, b, gA, gB, RPB2);  // bias folded into B (src side)
            k_em_edge<<<GE, 256>>>(goff + o * (NN + 1), gnbr + o * PER,
                                   gcef + o * PER, W + 128 * H);
        }
    }

    // 3x EdgeConv
    for (int L = 0; L < 3; L++) {
        k_gemm2<1, 0><<<G2, 128>>>(gx, ecw + L * 128 * H, ecb + L * H, gA, gB, RPB2);  // bias in A (dst side)
        k_ec_edge<<<GE, 256>>>(goff + 4 * (NN + 1), gnbr + EE);
    }

    // output head
    k_out<<<(NN * 10 + 255) / 256, 256>>>(ow, ob, (float*)d_out);
}

// round 2
// speedup vs baseline: 1.0778x; 1.0778x over previous
#include <cuda_runtime.h>

// Problem constants (fixed by the dataset)
constexpr int NN  = 50000;   // nodes
constexpr int EE  = 800000;  // edges
constexpr int PER = 200000;  // edges per emulsion order (EE/4)
constexpr int H   = 64;      // hidden dim

typedef unsigned long long u64;

// ---------------- scratch (static device globals; no allocation) ----------
__device__ float g_x[NN * H];        // node features
__device__ float g_A[NN * H];        // dst-side pre-GEMM
__device__ float g_B[NN * H];        // src-side pre-GEMM
__device__ int   g_deg[5 * NN];      // degrees: 4 src-slices + 1 dst
__device__ int   g_off[5 * (NN + 1)];
__device__ int   g_cur[5 * (NN + 1)];
__device__ int   g_nbr[2 * EE];      // [0,EE): src-CSR stores dst; [EE,2EE): dst-CSR stores src
__device__ float g_cef[EE];          // edge feature, src-CSR order

// ---------------- packed f32x2 helpers -------------------------------------
__device__ __forceinline__ u64 pk(float lo, float hi) {
    u64 r; asm("mov.b64 %0, {%1, %2};" : "=l"(r) : "f"(lo), "f"(hi)); return r;
}
__device__ __forceinline__ float2 unpk(u64 v) {
    float2 f; asm("mov.b64 {%0, %1}, %2;" : "=f"(f.x), "=f"(f.y) : "l"(v)); return f;
}
__device__ __forceinline__ void ffma2(u64& d, u64 a, u64 b) {
    asm("fma.rn.f32x2 %0, %1, %2, %0;" : "+l"(d) : "l"(a), "l"(b));
}

// ---------------- CSR build ------------------------------------------------
__global__ void k_zero(int* p, int n) {
    int i = blockIdx.x * blockDim.x + threadIdx.x;
    if (i < n) p[i] = 0;
}

__global__ void k_hist(const int* __restrict__ ei) {
    int e = blockIdx.x * blockDim.x + threadIdx.x;
    if (e >= EE) return;
    int s = ei[e], d = ei[EE + e];
    int sl = e / PER;
    atomicAdd(&g_deg[sl * NN + s], 1);
    atomicAdd(&g_deg[4 * NN + d], 1);
}

// grid = 5 blocks (one per array), block = 1024
__global__ void k_scan() {
    int a = blockIdx.x;
    const int* deg = g_deg + a * NN;
    int* off = g_off + a * (NN + 1);
    int* cur = g_cur + a * (NN + 1);
    int t = threadIdx.x;
    const int CH = (NN + 1023) / 1024;  // 49
    int begin = t * CH;
    int end = begin + CH; if (end > NN) end = NN; if (begin > NN) begin = NN;
    int s = 0;
    for (int i = begin; i < end; i++) s += deg[i];
    __shared__ int sh[1024];
    sh[t] = s;
    __syncthreads();
    for (int d = 1; d < 1024; d <<= 1) {
        int v = 0;
        if (t >= d) v = sh[t - d];
        __syncthreads();
        if (t >= d) sh[t] += v;
        __syncthreads();
    }
    int pre = (t == 0) ? 0 : sh[t - 1];
    for (int i = begin; i < end; i++) {
        off[i] = pre; cur[i] = pre;
        pre += deg[i];
    }
    if (t == 1023) off[NN] = sh[1023];
}

__global__ void k_scatter(const int* __restrict__ ei, const float* __restrict__ ef) {
    int e = blockIdx.x * blockDim.x + threadIdx.x;
    if (e >= EE) return;
    int s = ei[e], d = ei[EE + e];
    int sl = e / PER;
    int p = atomicAdd(&g_cur[sl * (NN + 1) + s], 1);
    int idx = sl * PER + p;
    g_nbr[idx] = d;
    g_cef[idx] = ef[e];
    int q = atomicAdd(&g_cur[4 * (NN + 1) + d], 1);
    g_nbr[EE + q] = s;
}

// ---------------- lin0 GEMM (K=10, small): out = relu(x@W+b) ---------------
// block = 64 threads, one output column per thread, weights in registers.
__global__ void k_gemm1_k10(const float* __restrict__ xin, const float* __restrict__ W,
                            const float* __restrict__ bias, float* __restrict__ out,
                            int rowsPerBlock) {
    const int K = 10;
    int t = threadIdx.x;  // column
    float w[K];
#pragma unroll
    for (int k = 0; k < K; k++) w[k] = W[k * H + t];
    float bv = bias[t];
    __shared__ float xs[4][K];
    int row0 = blockIdx.x * rowsPerBlock;
    int row1 = row0 + rowsPerBlock; if (row1 > NN) row1 = NN;
    for (int r = row0; r < row1; r += 4) {
        for (int i = t; i < 4 * K; i += 64) xs[i / K][i % K] = xin[r * K + i];
        __syncthreads();
        float a0 = bv, a1 = bv, a2 = bv, a3 = bv;
#pragma unroll
        for (int k = 0; k < K; k++) {
            float wv = w[k];
            a0 = fmaf(xs[0][k], wv, a0);
            a1 = fmaf(xs[1][k], wv, a1);
            a2 = fmaf(xs[2][k], wv, a2);
            a3 = fmaf(xs[3][k], wv, a3);
        }
        out[(r + 0) * H + t] = fmaxf(a0, 0.f);
        out[(r + 1) * H + t] = fmaxf(a1, 0.f);
        out[(r + 2) * H + t] = fmaxf(a2, 0.f);
        out[(r + 3) * H + t] = fmaxf(a3, 0.f);
        __syncthreads();
    }
}

// ---------------- lin GEMM (K=64), packed f32x2, 2 cols/thread, 1 warp -----
// out[N,64] = relu(x[N,64] @ W[64,64] + b).  Thread t owns cols t and t+32.
__global__ void __launch_bounds__(32) k_gemm1p(
        const float* __restrict__ xin, const float* __restrict__ W,
        const float* __restrict__ bias, float* __restrict__ out, int rowsPerBlock) {
    int t = threadIdx.x;
    int c0 = t, c1 = t + 32;
    u64 w0[32], w1[32];
#pragma unroll
    for (int k = 0; k < 32; k++) {
        w0[k] = pk(W[(2 * k) * H + c0], W[(2 * k + 1) * H + c0]);
        w1[k] = pk(W[(2 * k) * H + c1], W[(2 * k + 1) * H + c1]);
    }
    float b0 = bias[c0], b1 = bias[c1];
    __shared__ __align__(16) u64 xs[4][32];
    int row0 = blockIdx.x * rowsPerBlock;
    int row1 = row0 + rowsPerBlock; if (row1 > NN) row1 = NN;
    for (int r = row0; r < row1; r += 4) {
        const float4* src = (const float4*)(xin + r * H);
        ((float4*)xs)[t] = src[t];
        ((float4*)xs)[t + 32] = src[t + 32];
        __syncthreads();
        u64 a0 = 0, a1 = 0, a2 = 0, a3 = 0, e0 = 0, e1 = 0, e2 = 0, e3 = 0;
#pragma unroll
        for (int k2 = 0; k2 < 16; k2++) {
            ulonglong2 x0 = ((const ulonglong2*)xs[0])[k2];
            ulonglong2 x1 = ((const ulonglong2*)xs[1])[k2];
            ulonglong2 x2 = ((const ulonglong2*)xs[2])[k2];
            ulonglong2 x3 = ((const ulonglong2*)xs[3])[k2];
            u64 wa = w0[2 * k2], wb = w0[2 * k2 + 1];
            u64 wc = w1[2 * k2], wd = w1[2 * k2 + 1];
            ffma2(a0, x0.x, wa); ffma2(a0, x0.y, wb);
            ffma2(e0, x0.x, wc); ffma2(e0, x0.y, wd);
            ffma2(a1, x1.x, wa); ffma2(a1, x1.y, wb);
            ffma2(e1, x1.x, wc); ffma2(e1, x1.y, wd);
            ffma2(a2, x2.x, wa); ffma2(a2, x2.y, wb);
            ffma2(e2, x2.x, wc); ffma2(e2, x2.y, wd);
            ffma2(a3, x3.x, wa); ffma2(a3, x3.y, wb);
            ffma2(e3, x3.x, wc); ffma2(e3, x3.y, wd);
        }
        float2 f;
        f = unpk(a0); out[(r + 0) * H + c0] = fmaxf(f.x + f.y + b0, 0.f);
        f = unpk(a1); out[(r + 1) * H + c0] = fmaxf(f.x + f.y + b0, 0.f);
        f = unpk(a2); out[(r + 2) * H + c0] = fmaxf(f.x + f.y + b0, 0.f);
        f = unpk(a3); out[(r + 3) * H + c0] = fmaxf(f.x + f.y + b0, 0.f);
        f = unpk(e0); out[(r + 0) * H + c1] = fmaxf(f.x + f.y + b1, 0.f);
        f = unpk(e1); out[(r + 1) * H + c1] = fmaxf(f.x + f.y + b1, 0.f);
        f = unpk(e2); out[(r + 2) * H + c1] = fmaxf(f.x + f.y + b1, 0.f);
        f = unpk(e3); out[(r + 3) * H + c1] = fmaxf(f.x + f.y + b1, 0.f);
        __syncthreads();
    }
}

// ---------------- fused dual GEMM, packed f32x2, 2 cols/thread -------------
// A = x@(W[0:64]-W[64:128]) (+bias?),  B = x@W[64:128] (+bias?).
// block = 64 threads; thread c computes column c of BOTH A and B.
template <int BIAS_A, int BIAS_B>
__global__ void __launch_bounds__(64) k_gemm2(
        const float* __restrict__ xin, const float* __restrict__ W,
        const float* __restrict__ bias, float* __restrict__ outA,
        float* __restrict__ outB, int rowsPerBlock) {
    int c = threadIdx.x;
    u64 wA[32], wB[32];
#pragma unroll
    for (int k = 0; k < 32; k++) {
        float p0 = W[(H + 2 * k) * H + c], p1 = W[(H + 2 * k + 1) * H + c];
        wB[k] = pk(p0, p1);
        wA[k] = pk(W[(2 * k) * H + c] - p0, W[(2 * k + 1) * H + c] - p1);
    }
    float bA = BIAS_A ? bias[c] : 0.f;
    float bB = BIAS_B ? bias[c] : 0.f;
    __shared__ __align__(16) u64 xs[4][32];
    int row0 = blockIdx.x * rowsPerBlock;
    int row1 = row0 + rowsPerBlock; if (row1 > NN) row1 = NN;
    for (int r = row0; r < row1; r += 4) {
        const float4* src = (const float4*)(xin + r * H);
        ((float4*)xs)[c] = src[c];  // 64 float4 = 4 rows x 64 floats
        __syncthreads();
        u64 aA0 = 0, aA1 = 0, aA2 = 0, aA3 = 0;
        u64 aB0 = 0, aB1 = 0, aB2 = 0, aB3 = 0;
#pragma unroll
        for (int k2 = 0; k2 < 16; k2++) {
            ulonglong2 x0 = ((const ulonglong2*)xs[0])[k2];
            ulonglong2 x1 = ((const ulonglong2*)xs[1])[k2];
            ulonglong2 x2 = ((const ulonglong2*)xs[2])[k2];
            ulonglong2 x3 = ((const ulonglong2*)xs[3])[k2];
            u64 wa0 = wA[2 * k2], wa1 = wA[2 * k2 + 1];
            u64 wb0 = wB[2 * k2], wb1 = wB[2 * k2 + 1];
            ffma2(aA0, x0.x, wa0); ffma2(aA0, x0.y, wa1);
            ffma2(aB0, x0.x, wb0); ffma2(aB0, x0.y, wb1);
            ffma2(aA1, x1.x, wa0); ffma2(aA1, x1.y, wa1);
            ffma2(aB1, x1.x, wb0); ffma2(aB1, x1.y, wb1);
            ffma2(aA2, x2.x, wa0); ffma2(aA2, x2.y, wa1);
            ffma2(aB2, x2.x, wb0); ffma2(aB2, x2.y, wb1);
            ffma2(aA3, x3.x, wa0); ffma2(aA3, x3.y, wa1);
            ffma2(aB3, x3.x, wb0); ffma2(aB3, x3.y, wb1);
        }
        float2 f;
        f = unpk(aA0); outA[(r + 0) * H + c] = f.x + f.y + bA;
        f = unpk(aA1); outA[(r + 1) * H + c] = f.x + f.y + bA;
        f = unpk(aA2); outA[(r + 2) * H + c] = f.x + f.y + bA;
        f = unpk(aA3); outA[(r + 3) * H + c] = f.x + f.y + bA;
        f = unpk(aB0); outB[(r + 0) * H + c] = f.x + f.y + bB;
        f = unpk(aB1); outB[(r + 1) * H + c] = f.x + f.y + bB;
        f = unpk(aB2); outB[(r + 2) * H + c] = f.x + f.y + bB;
        f = unpk(aB3); outB[(r + 3) * H + c] = f.x + f.y + bB;
        __syncthreads();
    }
}

// ---------------- EmulsionConv edge pass (one order slice) -----------------
// 64-lane group per node n (aggregating at src):
//   x[n] = (x[n] + sum_e relu(A[dst_e] + B[n] + ef_e*w2)) / 2
__global__ void k_em_edge(const int* __restrict__ off, const int* __restrict__ nbr,
                          const float* __restrict__ cef, const float* __restrict__ w2) {
    int n = (blockIdx.x * blockDim.x + threadIdx.x) >> 6;
    int lane = threadIdx.x & 63;
    if (n >= NN) return;
    int e0 = off[n], e1 = off[n + 1];
    float yb = g_B[n * H + lane];
    float w2v = w2[lane];
    float a = 0.f;
    for (int e = e0; e < e1; e++) {
        int d = nbr[e];
        float f = cef[e];
        a += fmaxf(g_A[d * H + lane] + fmaf(f, w2v, yb), 0.f);
    }
    g_x[n * H + lane] = (g_x[n * H + lane] + a) * 0.5f;
}

// ---------------- EdgeConv edge pass ---------------------------------------
// 64-lane group per node n (aggregating at dst): x[n] = max(0, max_e (A[n]+B[src_e]))
__global__ void k_ec_edge(const int* __restrict__ off, const int* __restrict__ nbr) {
    int n = (blockIdx.x * blockDim.x + threadIdx.x) >> 6;
    int lane = threadIdx.x & 63;
    if (n >= NN) return;
    int e0 = off[n], e1 = off[n + 1];
    float za = g_A[n * H + lane];
    float a = 0.f;  // relu floor: max over messages of relu == max(0, max msg)
    for (int e = e0; e < e1; e++) {
        int s = nbr[e];
        a = fmaxf(a, za + g_B[s * H + lane]);
    }
    g_x[n * H + lane] = a;
}

// ---------------- output head: out[N,10] = x@ow[64,10] + ob -----------------
__global__ void k_out(const float* __restrict__ ow, const float* __restrict__ ob,
                      float* __restrict__ out) {
    __shared__ float w[64 * 10];
    __shared__ float b[10];
    int t = threadIdx.x;
    for (int i = t; i < 640; i += blockDim.x) w[i] = ow[i];
    if (t < 10) b[t] = ob[t];
    __syncthreads();
    int idx = blockIdx.x * blockDim.x + t;
    if (idx >= NN * 10) return;
    int n = idx / 10, c = idx % 10;
    float acc = b[c];
#pragma unroll
    for (int k = 0; k < 64; k++) acc = fmaf(g_x[n * H + k], w[k * 10 + c], acc);
    out[idx] = acc;
}

// ---------------- orchestration --------------------------------------------
extern "C" void kernel_launch(void* const* d_in, const int* in_sizes, int n_in,
                              void* d_out, int out_size) {
    const float* x0  = (const float*)d_in[0];
    const int*   ei  = (const int*)d_in[1];
    const float* ef  = (const float*)d_in[2];
    const float* lw[3] = {(const float*)d_in[3], (const float*)d_in[5], (const float*)d_in[7]};
    const float* lb[3] = {(const float*)d_in[4], (const float*)d_in[6], (const float*)d_in[8]};
    const float* emw = (const float*)d_in[9];   // [3,129,64]
    const float* emb = (const float*)d_in[10];  // [3,64]
    const float* ecw = (const float*)d_in[11];  // [3,128,64]
    const float* ecb = (const float*)d_in[12];  // [3,64]
    const float* ow  = (const float*)d_in[13];
    const float* ob  = (const float*)d_in[14];

    float *gx, *gA, *gB, *gcef;
    int *gdeg, *goff, *gnbr;
    cudaGetSymbolAddress((void**)&gx,   g_x);
    cudaGetSymbolAddress((void**)&gA,   g_A);
    cudaGetSymbolAddress((void**)&gB,   g_B);
    cudaGetSymbolAddress((void**)&gcef, g_cef);
    cudaGetSymbolAddress((void**)&gdeg, g_deg);
    cudaGetSymbolAddress((void**)&goff, g_off);
    cudaGetSymbolAddress((void**)&gnbr, g_nbr);

    // CSR build (per launch, deterministic workload)
    k_zero<<<(5 * NN + 255) / 256, 256>>>(gdeg, 5 * NN);
    k_hist<<<(EE + 255) / 256, 256>>>(ei);
    k_scan<<<5, 1024>>>();
    k_scatter<<<(EE + 255) / 256, 256>>>(ei, ef);

    const int RPB0 = 52;                          // lin0 (K=10)
    const int G0 = (NN + RPB0 - 1) / RPB0;
    const int RPB1 = 28;                          // lin packed (1 warp/block)
    const int G1 = (NN + RPB1 - 1) / RPB1;
    const int RPB2 = 68;                          // dual GEMM (64 thr/block)
    const int G2 = (NN + RPB2 - 1) / RPB2;
    const int GE = (NN * 64 + 255) / 256;         // 64-lane group per node

    // lin0 (K=10) + 3x (lin, EmulsionConv x4 orders)
    k_gemm1_k10<<<G0, 64>>>(x0, lw[0], lb[0], gx, RPB0);
    for (int L = 0; L < 3; L++) {
        if (L > 0) k_gemm1p<<<G1, 32>>>(gx, lw[L], lb[L], gx, RPB1);
        const float* W = emw + L * 129 * H;
        const float* b = emb + L * H;
        for (int o = 0; o < 4; o++) {
            k_gemm2<0, 1><<<G2, 64>>>(gx, W, b, gA, gB, RPB2);  // bias folded into B (src side)
            k_em_edge<<<GE, 256>>>(goff + o * (NN + 1), gnbr + o * PER,
                                   gcef + o * PER, W + 128 * H);
        }
    }

    // 3x EdgeConv
    for (int L = 0; L < 3; L++) {
        k_gemm2<1, 0><<<G2, 64>>>(gx, ecw + L * 128 * H, ecb + L * H, gA, gB, RPB2);  // bias in A (dst side)
        k_ec_edge<<<GE, 256>>>(goff + 4 * (NN + 1), gnbr + EE);
    }

    // output head
    k_out<<<(NN * 10 + 255) / 256, 256>>>(ow, ob, (float*)d_out);
}